// round 7
// baseline (speedup 1.0000x reference)
#include <cuda_runtime.h>
#include <math.h>

#define BB 256
#define TT 128
#define HH 256
#define FF 16
#define GG 1040   // 4*H + F

// ---- static device scratch ----
__device__ float g_xproj[TT * GG * BB];   // [t][g][b]
__device__ float g_h[2][HH * BB];         // [j][b], double buffered (no init needed)
__device__ unsigned g_bars[8 * 32];       // per-b-group barrier counters, padded 128B

__device__ __forceinline__ float hsig(float x) {
    return __saturatef(x * 0.16666667f + 0.5f);
}
__device__ __forceinline__ float ftanh(float x) {
    float e = __expf(2.0f * x);
    return 1.0f - __fdividef(2.0f, e + 1.0f);
}

// ---------------- phase 0: input projection ----------------
// xproj[t][g][b] = sum_k X[b,t,k] * W[k,g] + bias[g]
__global__ void proj_kernel(
    const float* __restrict__ sig, const float* __restrict__ met,
    const float* __restrict__ Wis, const float* __restrict__ Wss, const float* __restrict__ Wfs,
    const float* __restrict__ Wcs, const float* __restrict__ Wos,
    const float* __restrict__ Wim, const float* __restrict__ Wsm, const float* __restrict__ Wfm,
    const float* __restrict__ Wcm, const float* __restrict__ Wom,
    const float* __restrict__ b_i, const float* __restrict__ b_ste, const float* __restrict__ b_fre,
    const float* __restrict__ b_c, const float* __restrict__ b_o)
{
    __shared__ float A_s[96 * 64];   // [k][b]
    __shared__ float B_s[96 * 64];   // [k][n]
    const int n0 = blockIdx.x * 64;
    const int b0 = blockIdx.y * 64;
    const int t  = blockIdx.z;
    const int tid = threadIdx.x;

    // reset persistent-kernel barriers (stream order: proj completes before persist)
    if (blockIdx.x == 0 && blockIdx.y == 0 && blockIdx.z == 0 && tid < 8)
        g_bars[tid * 32] = 0u;

    for (int idx = tid; idx < 64 * 96; idx += 128) {
        int b = idx / 96, k = idx - b * 96;
        float v = (k < 64) ? sig[((b0 + b) * TT + t) * 64 + k]
                           : met[((b0 + b) * TT + t) * 32 + (k - 64)];
        A_s[k * 64 + b] = v;
    }
    for (int idx = tid; idx < 96 * 64; idx += 128) {
        int k = idx >> 6, n = idx & 63;
        int g = n0 + n;
        float v = 0.f;
        if (g < 1024) {
            int gate = g >> 8, j = g & 255;
            const float* Ws = (gate == 0) ? Wis : (gate == 1) ? Wss : (gate == 2) ? Wcs : Wos;
            const float* Wm = (gate == 0) ? Wim : (gate == 1) ? Wsm : (gate == 2) ? Wcm : Wom;
            v = (k < 64) ? Ws[k * 256 + j] : Wm[(k - 64) * 256 + j];
        } else if (g < GG) {
            int f = g - 1024;
            v = (k < 64) ? Wfs[k * 16 + f] : Wfm[(k - 64) * 16 + f];
        }
        B_s[k * 64 + n] = v;
    }
    __syncthreads();

    const int tm = tid & 7, tn = tid >> 3;
    const int mb = tm * 8, nb = tn * 4;
    float acc[8][4] = {};
    for (int k = 0; k < 96; k++) {
        float4 a0 = *(const float4*)&A_s[k * 64 + mb];
        float4 a1 = *(const float4*)&A_s[k * 64 + mb + 4];
        float4 bv = *(const float4*)&B_s[k * 64 + nb];
        float am[8] = {a0.x, a0.y, a0.z, a0.w, a1.x, a1.y, a1.z, a1.w};
#pragma unroll
        for (int i = 0; i < 8; i++) {
            acc[i][0] += am[i] * bv.x; acc[i][1] += am[i] * bv.y;
            acc[i][2] += am[i] * bv.z; acc[i][3] += am[i] * bv.w;
        }
    }
#pragma unroll
    for (int q = 0; q < 4; q++) {
        int g = n0 + nb + q;
        if (g >= GG) continue;
        float bias;
        if (g < 1024) {
            int gate = g >> 8, j = g & 255;
            bias = (gate == 0) ? b_i[j] : (gate == 1) ? b_ste[j] : (gate == 2) ? b_c[j] : b_o[j];
        } else {
            bias = b_fre[g - 1024];
        }
        float4 w0, w1;
        w0.x = acc[0][q] + bias; w0.y = acc[1][q] + bias;
        w0.z = acc[2][q] + bias; w0.w = acc[3][q] + bias;
        w1.x = acc[4][q] + bias; w1.y = acc[5][q] + bias;
        w1.z = acc[6][q] + bias; w1.w = acc[7][q] + bias;
        float* dst = &g_xproj[(t * GG + g) * BB + b0 + mb];
        *(float4*)dst = w0;
        *(float4*)(dst + 4) = w1;
    }
}

// ---------------- persistent recurrence kernel ----------------
// 128 CTAs (8 b-groups x 16 j-tiles), 256 threads, all 128 steps + output head.
// Groups are fully independent (recurrence decomposes by batch) -> per-group barriers.
#define PS_U     0                        // [k=256][80]: 0-63 gates (gate*16+jj), 64-79 fre
#define PS_H     (PS_U + 256 * 80)        // [k=256][36]
#define PS_GT    (PS_H + 256 * 36)        // [80][33]  GEMM outputs [g][b]
#define PS_X     (PS_GT + 80 * 33)        // 2 x [80][33] xproj double buffer
#define PS_RE    (PS_X + 2 * 80 * 33)     // [128][16] cos table
#define PS_IM    (PS_RE + 2048)           // [128][16] sin table
#define PS_UA    (PS_IM + 2048)
#define PS_BA    (PS_UA + 16)
#define PS_TOTAL (PS_BA + 16)

__global__ void __launch_bounds__(256, 1) persist_kernel(
    const float* __restrict__ U_i, const float* __restrict__ U_ste,
    const float* __restrict__ U_c, const float* __restrict__ U_o,
    const float* __restrict__ U_fre, const float* __restrict__ U_a,
    const float* __restrict__ b_a,
    const float* __restrict__ W_p, const float* __restrict__ b_p,
    const float* __restrict__ fc_w, const float* __restrict__ fc_b,
    float* __restrict__ out)
{
    extern __shared__ float sm[];
    float* U_s  = sm + PS_U;
    float* h_s  = sm + PS_H;
    float* gt_s = sm + PS_GT;
    float* x_s  = sm + PS_X;          // two buffers of 80*33
    float* re_t = sm + PS_RE;
    float* im_t = sm + PS_IM;
    float* Ua_s = sm + PS_UA;
    float* ba_s = sm + PS_BA;

    const int tid = threadIdx.x;
    const int bt = blockIdx.x & 7, jt = blockIdx.x >> 3;
    const int b0 = bt * 32, j0 = jt * 16;
    unsigned* my_bar = &g_bars[bt * 32];

    // ---- one-time staging ----
    for (int idx = tid; idx < 256 * 64; idx += 256) {
        int k = idx >> 6, g = idx & 63;
        int gate = g >> 4, jj = g & 15;
        const float* U = (gate == 0) ? U_i : (gate == 1) ? U_ste : (gate == 2) ? U_c : U_o;
        U_s[k * 80 + g] = U[k * 256 + j0 + jj];
    }
    for (int idx = tid; idx < 256 * 16; idx += 256) {
        int k = idx >> 4, f = idx & 15;
        U_s[k * 80 + 64 + f] = U_fre[k * 16 + f];
    }
    for (int idx = tid; idx < TT * 16; idx += 256) {
        int tt = idx >> 4, f = idx & 15;
        float ang = 6.2831855f * (float)(tt + 1) * ((float)f * 0.0625f);
        float sv, cv;
        sincosf(ang, &sv, &cv);
        re_t[idx] = cv; im_t[idx] = sv;
    }
    if (tid < 16) { Ua_s[tid] = U_a[tid]; ba_s[tid] = b_a[j0 + tid]; }

    // ---- prefetch xproj for t=0 into buffer 0 (vectorized) ----
    for (int idx4 = tid; idx4 < 640; idx4 += 256) {
        int g = idx4 >> 3, bq = idx4 & 7;        // g in [0,80), 8 float4 per g
        int src_g = (g < 64) ? ((g >> 4) * 256 + j0 + (g & 15)) : (1024 + (g - 64));
        float4 v = *(const float4*)&g_xproj[src_g * BB + b0 + bq * 4];
        x_s[g * 33 + bq * 4 + 0] = v.x; x_s[g * 33 + bq * 4 + 1] = v.y;
        x_s[g * 33 + bq * 4 + 2] = v.z; x_s[g * 33 + bq * 4 + 3] = v.w;
    }

    // ---- S state in registers: 2 consecutive b x 16 f ----
    float Sre[2][16], Sim[2][16];
#pragma unroll
    for (int p = 0; p < 2; p++)
#pragma unroll
        for (int f = 0; f < 16; f++) { Sre[p][f] = 0.f; Sim[p][f] = 0.f; }

    const int c_jj = tid >> 4;          // 0..15
    const int c_b2 = (tid & 15) * 2;    // consecutive b pair

    for (int t = 0; t < TT; t++) {
        // ---- stage h (float4 ldcg; zeros at t=0) ----
        if (t == 0) {
            const float4 z = make_float4(0.f, 0.f, 0.f, 0.f);
            for (int idx = tid; idx < 2048; idx += 256) {
                int k = idx >> 3, q = idx & 7;
                *(float4*)&h_s[k * 36 + q * 4] = z;
            }
        } else {
            const float* hin = &g_h[t & 1][0];
            for (int idx = tid; idx < 2048; idx += 256) {
                int k = idx >> 3, q = idx & 7;
                float4 v = __ldcg((const float4*)&hin[k * 256 + b0 + q * 4]);
                *(float4*)&h_s[k * 36 + q * 4] = v;
            }
        }
        __syncthreads();

        float* xc = x_s + (t & 1) * (80 * 33);        // consume buffer
        float* xn = x_s + ((t + 1) & 1) * (80 * 33);  // prefetch buffer

        if (tid < 128) {
            // ---- gates GEMM: 32b x 64g, 4b x 4g per thread ----
            const int bg = tid >> 4, gg = tid & 15;
            const float* hp = h_s + bg * 4;
            const float* up = U_s + gg * 4;
            float acc[4][4] = {};
#pragma unroll 4
            for (int k = 0; k < 256; k++) {
                float4 hv = *(const float4*)(hp + k * 36);
                float4 uv = *(const float4*)(up + k * 80);
                acc[0][0] += hv.x * uv.x; acc[0][1] += hv.x * uv.y; acc[0][2] += hv.x * uv.z; acc[0][3] += hv.x * uv.w;
                acc[1][0] += hv.y * uv.x; acc[1][1] += hv.y * uv.y; acc[1][2] += hv.y * uv.z; acc[1][3] += hv.y * uv.w;
                acc[2][0] += hv.z * uv.x; acc[2][1] += hv.z * uv.y; acc[2][2] += hv.z * uv.z; acc[2][3] += hv.z * uv.w;
                acc[3][0] += hv.w * uv.x; acc[3][1] += hv.w * uv.y; acc[3][2] += hv.w * uv.z; acc[3][3] += hv.w * uv.w;
            }
#pragma unroll
            for (int q = 0; q < 4; q++)
#pragma unroll
                for (int i = 0; i < 4; i++)
                    gt_s[(gg * 4 + q) * 33 + bg * 4 + i] = acc[i][q];
        } else {
            const int s = tid - 128;
            // ---- prefetch next step's xproj (vectorized, independent of h) ----
            if (t + 1 < TT) {
                const int xt = (t + 1) * GG * BB;
                for (int idx4 = s; idx4 < 640; idx4 += 128) {
                    int g = idx4 >> 3, bq = idx4 & 7;
                    int src_g = (g < 64) ? ((g >> 4) * 256 + j0 + (g & 15)) : (1024 + (g - 64));
                    float4 v = *(const float4*)&g_xproj[xt + src_g * BB + b0 + bq * 4];
                    xn[g * 33 + bq * 4 + 0] = v.x; xn[g * 33 + bq * 4 + 1] = v.y;
                    xn[g * 33 + bq * 4 + 2] = v.z; xn[g * 33 + bq * 4 + 3] = v.w;
                }
            }
            // ---- fre matvec: 32b x 16f, 1b x 4f per thread ----
            const int fb = s >> 2, f0 = (s & 3) * 4;
            const float* up = U_s + 64 + f0;
            float fa0 = 0.f, fa1 = 0.f, fa2 = 0.f, fa3 = 0.f;
#pragma unroll 4
            for (int k = 0; k < 256; k++) {
                float hk = h_s[k * 36 + fb];
                float4 uv = *(const float4*)(up + k * 80);
                fa0 += hk * uv.x; fa1 += hk * uv.y; fa2 += hk * uv.z; fa3 += hk * uv.w;
            }
            gt_s[(64 + f0 + 0) * 33 + fb] = fa0;
            gt_s[(64 + f0 + 1) * 33 + fb] = fa1;
            gt_s[(64 + f0 + 2) * 33 + fb] = fa2;
            gt_s[(64 + f0 + 3) * 33 + fb] = fa3;
        }
        __syncthreads();

        // ---- consumer: S update (registers) + h output ----
        float* hout = &g_h[(t & 1) ^ 1][0];
        const float* ret = re_t + t * 16;
        const float* imt = im_t + t * 16;
        float hres[2];
#pragma unroll
        for (int p = 0; p < 2; p++) {
            const int b = c_b2 + p;
            float gi  = hsig(gt_s[(     c_jj) * 33 + b] + xc[(     c_jj) * 33 + b]);
            float ste = hsig(gt_s[(16 + c_jj) * 33 + b] + xc[(16 + c_jj) * 33 + b]);
            float cg  = gi * ftanh(gt_s[(32 + c_jj) * 33 + b] + xc[(32 + c_jj) * 33 + b]);
            float o   = hsig(gt_s[(48 + c_jj) * 33 + b] + xc[(48 + c_jj) * 33 + b]);
            float Aa = 0.f;
#pragma unroll
            for (int f = 0; f < 16; f++) {
                float fre = hsig(gt_s[(64 + f) * 33 + b] + xc[(64 + f) * 33 + b]);
                float fv = ste * fre;
                float nr = fv * Sre[p][f] + cg * ret[f];
                float ni = fv * Sim[p][f] + cg * imt[f];
                Sre[p][f] = nr; Sim[p][f] = ni;
                Aa += (nr * nr + ni * ni) * Ua_s[f];
            }
            float a = ftanh(Aa + ba_s[c_jj]);
            hres[p] = o * a;
        }
        __stcg((float2*)&hout[(j0 + c_jj) * 256 + b0 + c_b2], make_float2(hres[0], hres[1]));

        // ---- per-group barrier (16 CTAs sharing this b-tile) ----
        __threadfence();
        __syncthreads();
        if (tid == 0) {
            atomicAdd(my_bar, 1u);
            const unsigned target = 16u * (unsigned)(t + 1);
            while (*(volatile unsigned*)my_bar < target) { }
        }
        __syncthreads();
    }

    // ---- output head: CTA (bt, jt=0) computes its group's 32 outputs ----
    if (jt == 0) {
        // partial sums: thread tid handles b = b0 + (tid&31), j-range (tid>>5)*32..+32
        const float* h = &g_h[0][0];
        const int b = b0 + (tid & 31);
        const int jr = (tid >> 5) * 32;
        float s = 0.f;
#pragma unroll 8
        for (int j = jr; j < jr + 32; j++) s += __ldcg(&h[j * 256 + b]) * W_p[j];
        gt_s[(tid >> 5) * 33 + (tid & 31)] = s;   // reuse gt_s as scratch
        __syncthreads();
        if (tid < 32) {
            float acc = 0.f;
#pragma unroll
            for (int q = 0; q < 8; q++) acc += gt_s[q * 33 + tid];
            float p = acc + b_p[0];
            out[b0 + tid] = p * fc_w[0] + fc_b[0];
        }
    }
}

// ---------------- launch ----------------
extern "C" void kernel_launch(void* const* d_in, const int* in_sizes, int n_in,
                              void* d_out, int out_size)
{
    const float* sig  = (const float*)d_in[0];
    const float* met  = (const float*)d_in[1];
    const float* Wis  = (const float*)d_in[2];
    const float* Wss  = (const float*)d_in[3];
    const float* Wfs  = (const float*)d_in[4];
    const float* Wcs  = (const float*)d_in[5];
    const float* Wos  = (const float*)d_in[6];
    const float* Wim  = (const float*)d_in[7];
    const float* Wsm  = (const float*)d_in[8];
    const float* Wfm  = (const float*)d_in[9];
    const float* Wcm  = (const float*)d_in[10];
    const float* Wom  = (const float*)d_in[11];
    const float* U_i  = (const float*)d_in[12];
    const float* b_i  = (const float*)d_in[13];
    const float* U_ste= (const float*)d_in[14];
    const float* b_ste= (const float*)d_in[15];
    const float* U_fre= (const float*)d_in[16];
    const float* b_fre= (const float*)d_in[17];
    const float* U_c  = (const float*)d_in[18];
    const float* b_c  = (const float*)d_in[19];
    const float* U_o  = (const float*)d_in[20];
    const float* b_o  = (const float*)d_in[21];
    const float* U_a  = (const float*)d_in[22];
    const float* b_a  = (const float*)d_in[23];
    const float* W_p  = (const float*)d_in[24];
    const float* b_p  = (const float*)d_in[25];
    const float* fc_w = (const float*)d_in[26];
    const float* fc_b = (const float*)d_in[27];
    float* out = (float*)d_out;

    cudaFuncSetAttribute(persist_kernel, cudaFuncAttributeMaxDynamicSharedMemorySize,
                         PS_TOTAL * 4);

    proj_kernel<<<dim3(17, 4, 128), 128>>>(sig, met, Wis, Wss, Wfs, Wcs, Wos,
                                           Wim, Wsm, Wfm, Wcm, Wom,
                                           b_i, b_ste, b_fre, b_c, b_o);
    persist_kernel<<<128, 256, PS_TOTAL * 4>>>(U_i, U_ste, U_c, U_o, U_fre, U_a, b_a,
                                               W_p, b_p, fc_w, fc_b, out);
}

// round 9
// speedup vs baseline: 1.0766x; 1.0766x over previous
#include <cuda_runtime.h>
#include <math.h>

#define BB 256
#define TT 128
#define HH 256
#define FF 16
#define GG 1040   // 4*H + F

// ---- static device scratch ----
__device__ float g_xproj[TT * GG * BB];   // [t][g][b]
__device__ float g_h[2][HH * BB];         // [j][b], double buffered
__device__ unsigned g_bars[16 * 32];      // per-group barrier counters, padded 128B

__device__ __forceinline__ float hsig(float x) {
    return __saturatef(x * 0.16666667f + 0.5f);
}
__device__ __forceinline__ float ftanh(float x) {
    float e = __expf(2.0f * x);
    return 1.0f - __fdividef(2.0f, e + 1.0f);
}

// ---------------- phase 0: input projection ----------------
__global__ void proj_kernel(
    const float* __restrict__ sig, const float* __restrict__ met,
    const float* __restrict__ Wis, const float* __restrict__ Wss, const float* __restrict__ Wfs,
    const float* __restrict__ Wcs, const float* __restrict__ Wos,
    const float* __restrict__ Wim, const float* __restrict__ Wsm, const float* __restrict__ Wfm,
    const float* __restrict__ Wcm, const float* __restrict__ Wom,
    const float* __restrict__ b_i, const float* __restrict__ b_ste, const float* __restrict__ b_fre,
    const float* __restrict__ b_c, const float* __restrict__ b_o)
{
    __shared__ float A_s[96 * 64];   // [k][b]
    __shared__ float B_s[96 * 64];   // [k][n]
    const int n0 = blockIdx.x * 64;
    const int b0 = blockIdx.y * 64;
    const int t  = blockIdx.z;
    const int tid = threadIdx.x;

    // reset persistent-kernel barriers (stream order: proj completes before persist)
    if (blockIdx.x == 0 && blockIdx.y == 0 && blockIdx.z == 0 && tid < 16)
        g_bars[tid * 32] = 0u;

    for (int idx = tid; idx < 64 * 96; idx += 128) {
        int b = idx / 96, k = idx - b * 96;
        float v = (k < 64) ? sig[((b0 + b) * TT + t) * 64 + k]
                           : met[((b0 + b) * TT + t) * 32 + (k - 64)];
        A_s[k * 64 + b] = v;
    }
    for (int idx = tid; idx < 96 * 64; idx += 128) {
        int k = idx >> 6, n = idx & 63;
        int g = n0 + n;
        float v = 0.f;
        if (g < 1024) {
            int gate = g >> 8, j = g & 255;
            const float* Ws = (gate == 0) ? Wis : (gate == 1) ? Wss : (gate == 2) ? Wcs : Wos;
            const float* Wm = (gate == 0) ? Wim : (gate == 1) ? Wsm : (gate == 2) ? Wcm : Wom;
            v = (k < 64) ? Ws[k * 256 + j] : Wm[(k - 64) * 256 + j];
        } else if (g < GG) {
            int f = g - 1024;
            v = (k < 64) ? Wfs[k * 16 + f] : Wfm[(k - 64) * 16 + f];
        }
        B_s[k * 64 + n] = v;
    }
    __syncthreads();

    const int tm = tid & 7, tn = tid >> 3;
    const int mb = tm * 8, nb = tn * 4;
    float acc[8][4] = {};
    for (int k = 0; k < 96; k++) {
        float4 a0 = *(const float4*)&A_s[k * 64 + mb];
        float4 a1 = *(const float4*)&A_s[k * 64 + mb + 4];
        float4 bv = *(const float4*)&B_s[k * 64 + nb];
        float am[8] = {a0.x, a0.y, a0.z, a0.w, a1.x, a1.y, a1.z, a1.w};
#pragma unroll
        for (int i = 0; i < 8; i++) {
            acc[i][0] += am[i] * bv.x; acc[i][1] += am[i] * bv.y;
            acc[i][2] += am[i] * bv.z; acc[i][3] += am[i] * bv.w;
        }
    }
#pragma unroll
    for (int q = 0; q < 4; q++) {
        int g = n0 + nb + q;
        if (g >= GG) continue;
        float bias;
        if (g < 1024) {
            int gate = g >> 8, j = g & 255;
            bias = (gate == 0) ? b_i[j] : (gate == 1) ? b_ste[j] : (gate == 2) ? b_c[j] : b_o[j];
        } else {
            bias = b_fre[g - 1024];
        }
        float4 w0, w1;
        w0.x = acc[0][q] + bias; w0.y = acc[1][q] + bias;
        w0.z = acc[2][q] + bias; w0.w = acc[3][q] + bias;
        w1.x = acc[4][q] + bias; w1.y = acc[5][q] + bias;
        w1.z = acc[6][q] + bias; w1.w = acc[7][q] + bias;
        float* dst = &g_xproj[(t * GG + g) * BB + b0 + mb];
        *(float4*)dst = w0;
        *(float4*)(dst + 4) = w1;
    }
}

// ---------------- persistent recurrence kernel ----------------
// 128 CTAs = 16 groups (16 b each) x 8 ranks (32 j each), 256 threads.
// Proven step skeleton: stage h -> sync -> GEMM/helper -> sync -> consumer ->
// fence -> sync -> arrive/poll -> sync. No conditional waits.
#define PS_U     0                        // [k=256][144]: 0-127 gates (gate*32+jj), 128-143 fre
#define PS_H     (PS_U + 256 * 144)       // [k=256][16]
#define PS_GT    (PS_H + 256 * 16)        // [144][20]
#define PS_X     (PS_GT + 144 * 20)       // 2 x [144][16] xproj double buffer
#define PS_RE    (PS_X + 2 * 144 * 16)    // [128][16] cos
#define PS_IM    (PS_RE + 2048)           // [128][16] sin
#define PS_UA    (PS_IM + 2048)
#define PS_BA    (PS_UA + 16)
#define PS_TOTAL (PS_BA + 32)

__global__ void __launch_bounds__(256, 1) persist_kernel(
    const float* __restrict__ U_i, const float* __restrict__ U_ste,
    const float* __restrict__ U_c, const float* __restrict__ U_o,
    const float* __restrict__ U_fre, const float* __restrict__ U_a,
    const float* __restrict__ b_a,
    const float* __restrict__ W_p, const float* __restrict__ b_p,
    const float* __restrict__ fc_w, const float* __restrict__ fc_b,
    float* __restrict__ out)
{
    extern __shared__ float sm[];
    float* U_s  = sm + PS_U;
    float* h_s  = sm + PS_H;
    float* gt_s = sm + PS_GT;
    float* x_s  = sm + PS_X;
    float* re_t = sm + PS_RE;
    float* im_t = sm + PS_IM;
    float* Ua_s = sm + PS_UA;
    float* ba_s = sm + PS_BA;

    const int tid = threadIdx.x;
    const int grp = blockIdx.x & 15;     // b-group (16 b)
    const int rnk = blockIdx.x >> 4;     // j-rank (32 j)
    const int b0 = grp * 16, j0 = rnk * 32;
    unsigned* my_bar = &g_bars[grp * 32];

    // ---- one-time staging: U gate columns for this j-slice ----
    for (int idx = tid; idx < 256 * 128; idx += 256) {
        int k = idx >> 7, c = idx & 127;
        int gate = c >> 5, jj = c & 31;
        const float* U = (gate == 0) ? U_i : (gate == 1) ? U_ste : (gate == 2) ? U_c : U_o;
        U_s[k * 144 + c] = U[k * 256 + j0 + jj];
    }
    for (int idx = tid; idx < 256 * 16; idx += 256) {
        int k = idx >> 4, f = idx & 15;
        U_s[k * 144 + 128 + f] = U_fre[k * 16 + f];
    }
    for (int idx = tid; idx < TT * 16; idx += 256) {
        int tt = idx >> 4, f = idx & 15;
        float ang = 6.2831855f * (float)(tt + 1) * ((float)f * 0.0625f);
        float sv, cv;
        sincosf(ang, &sv, &cv);
        re_t[idx] = cv; im_t[idx] = sv;
    }
    if (tid < 16) Ua_s[tid] = U_a[tid];
    if (tid < 32) ba_s[tid] = b_a[j0 + tid];

    // ---- prefetch xproj for t=0 into parity-0 buffer ----
    for (int idx4 = tid; idx4 < 576; idx4 += 256) {
        int g = idx4 >> 2, bq = idx4 & 3;
        int src_g = (g < 128) ? ((g >> 5) * 256 + j0 + (g & 31)) : (1024 + (g - 128));
        float4 v = *(const float4*)&g_xproj[src_g * BB + b0 + bq * 4];
        *(float4*)&x_s[g * 16 + bq * 4] = v;
    }

    // ---- S state in registers: 2 consecutive b x 16 f per thread ----
    float Sre[2][16], Sim[2][16];
#pragma unroll
    for (int p = 0; p < 2; p++)
#pragma unroll
        for (int f = 0; f < 16; f++) { Sre[p][f] = 0.f; Sim[p][f] = 0.f; }

    const int c_jj = tid >> 3;          // 0..31
    const int c_b2 = (tid & 7) * 2;     // consecutive b pair

    for (int t = 0; t < TT; t++) {
        // ---- stage h(t): [k=256][16 b] (zeros at t=0) ----
        if (t == 0) {
            const float4 z = make_float4(0.f, 0.f, 0.f, 0.f);
            for (int idx = tid; idx < 1024; idx += 256)
                *(float4*)&h_s[idx * 4] = z;
        } else {
            const float* hin = &g_h[t & 1][0];
            for (int idx = tid; idx < 1024; idx += 256) {
                int k = idx >> 2, q = idx & 3;
                float4 v = __ldcg((const float4*)&hin[k * 256 + b0 + q * 4]);
                *(float4*)&h_s[k * 16 + q * 4] = v;
            }
        }
        __syncthreads();

        const float* xc = x_s + (t & 1) * (144 * 16);
        float* xn = x_s + ((t + 1) & 1) * (144 * 16);

        if (tid < 128) {
            // ---- gates GEMM: 16b x 128g, 4b x 4g per thread ----
            const int bg = tid >> 5, gg = tid & 31;
            const float* hp = h_s + bg * 4;
            const float* up = U_s + gg * 4;
            float acc[4][4] = {};
#pragma unroll 4
            for (int k = 0; k < 256; k++) {
                float4 hv = *(const float4*)(hp + k * 16);
                float4 uv = *(const float4*)(up + k * 144);
                acc[0][0] += hv.x * uv.x; acc[0][1] += hv.x * uv.y; acc[0][2] += hv.x * uv.z; acc[0][3] += hv.x * uv.w;
                acc[1][0] += hv.y * uv.x; acc[1][1] += hv.y * uv.y; acc[1][2] += hv.y * uv.z; acc[1][3] += hv.y * uv.w;
                acc[2][0] += hv.z * uv.x; acc[2][1] += hv.z * uv.y; acc[2][2] += hv.z * uv.z; acc[2][3] += hv.z * uv.w;
                acc[3][0] += hv.w * uv.x; acc[3][1] += hv.w * uv.y; acc[3][2] += hv.w * uv.z; acc[3][3] += hv.w * uv.w;
            }
#pragma unroll
            for (int q = 0; q < 4; q++) {
                float4 w;
                w.x = acc[0][q]; w.y = acc[1][q]; w.z = acc[2][q]; w.w = acc[3][q];
                *(float4*)&gt_s[(gg * 4 + q) * 20 + bg * 4] = w;
            }
        } else {
            const int s = tid - 128;
            // ---- batch-issue x(t+1) LDGs into regs ----
            float4 r[5];
            int nld = 0;
            if (t + 1 < TT) {
                const int xt = (t + 1) * GG * BB;
#pragma unroll
                for (int i = 0; i < 5; i++) {
                    int idx4 = s + i * 128;
                    if (idx4 < 576) {
                        int g = idx4 >> 2, bq = idx4 & 3;
                        int src_g = (g < 128) ? ((g >> 5) * 256 + j0 + (g & 31)) : (1024 + (g - 128));
                        r[i] = *(const float4*)&g_xproj[xt + src_g * BB + b0 + bq * 4];
                        nld = i + 1;
                    }
                }
            }
            // ---- fre matvec: 16b x 16f, 2 (b,f) pairs per thread ----
            const int f = s >> 3, b = s & 7;
            const float* up = U_s + 128 + f;
            float fa0 = 0.f, fa1 = 0.f;
#pragma unroll 4
            for (int k = 0; k < 256; k++) {
                float u = up[k * 144];
                fa0 += h_s[k * 16 + b] * u;
                fa1 += h_s[k * 16 + b + 8] * u;
            }
            gt_s[(128 + f) * 20 + b]     = fa0;
            gt_s[(128 + f) * 20 + b + 8] = fa1;
            // ---- store x(t+1) regs -> smem ----
            if (t + 1 < TT) {
#pragma unroll
                for (int i = 0; i < 5; i++) {
                    int idx4 = s + i * 128;
                    if (i < nld && idx4 < 576) {
                        int g = idx4 >> 2, bq = idx4 & 3;
                        *(float4*)&xn[g * 16 + bq * 4] = r[i];
                    }
                }
            }
        }
        __syncthreads();

        // ---- consumer: 2 (b, jj) pairs per thread, S in registers ----
        {
            float* hout = &g_h[(t & 1) ^ 1][0];
            const float* ret = re_t + t * 16;
            const float* imt = im_t + t * 16;
            float hres[2];
#pragma unroll
            for (int p = 0; p < 2; p++) {
                const int b = c_b2 + p;
                float gi  = hsig(gt_s[(      c_jj) * 20 + b] + xc[(      c_jj) * 16 + b]);
                float ste = hsig(gt_s[( 32 + c_jj) * 20 + b] + xc[( 32 + c_jj) * 16 + b]);
                float cg  = gi * ftanh(gt_s[( 64 + c_jj) * 20 + b] + xc[( 64 + c_jj) * 16 + b]);
                float o   = hsig(gt_s[( 96 + c_jj) * 20 + b] + xc[( 96 + c_jj) * 16 + b]);
                float Aa = 0.f;
#pragma unroll
                for (int f = 0; f < 16; f++) {
                    float fre = hsig(gt_s[(128 + f) * 20 + b] + xc[(128 + f) * 16 + b]);
                    float fv = ste * fre;
                    float nr = fv * Sre[p][f] + cg * ret[f];
                    float ni = fv * Sim[p][f] + cg * imt[f];
                    Sre[p][f] = nr; Sim[p][f] = ni;
                    Aa += (nr * nr + ni * ni) * Ua_s[f];
                }
                float a = ftanh(Aa + ba_s[c_jj]);
                hres[p] = o * a;
            }
            __stcg((float2*)&hout[(j0 + c_jj) * 256 + b0 + c_b2], make_float2(hres[0], hres[1]));
        }

        // ---- per-group barrier (8 CTAs sharing this b-group) ----
        __threadfence();
        __syncthreads();
        if (tid == 0) {
            atomicAdd(my_bar, 1u);
            const unsigned target = 8u * (unsigned)(t + 1);
            while (*(volatile unsigned*)my_bar < target) { }
        }
        __syncthreads();
    }

    // ---- output head: rank-0 CTA of each group computes its 16 outputs ----
    if (rnk == 0) {
        const float* h = &g_h[0][0];   // h(128): t=127 wrote buffer 0
        const int b = b0 + (tid & 15);
        const int jr = (tid >> 4) * 16;
        float s = 0.f;
#pragma unroll 4
        for (int j = jr; j < jr + 16; j++) s += __ldcg(&h[j * 256 + b]) * W_p[j];
        gt_s[(tid >> 4) * 20 + (tid & 15)] = s;
        __syncthreads();
        if (tid < 16) {
            float acc = 0.f;
#pragma unroll
            for (int q = 0; q < 16; q++) acc += gt_s[q * 20 + tid];
            float p = acc + b_p[0];
            out[b0 + tid] = p * fc_w[0] + fc_b[0];
        }
    }
}

// ---------------- launch ----------------
extern "C" void kernel_launch(void* const* d_in, const int* in_sizes, int n_in,
                              void* d_out, int out_size)
{
    const float* sig  = (const float*)d_in[0];
    const float* met  = (const float*)d_in[1];
    const float* Wis  = (const float*)d_in[2];
    const float* Wss  = (const float*)d_in[3];
    const float* Wfs  = (const float*)d_in[4];
    const float* Wcs  = (const float*)d_in[5];
    const float* Wos  = (const float*)d_in[6];
    const float* Wim  = (const float*)d_in[7];
    const float* Wsm  = (const float*)d_in[8];
    const float* Wfm  = (const float*)d_in[9];
    const float* Wcm  = (const float*)d_in[10];
    const float* Wom  = (const float*)d_in[11];
    const float* U_i  = (const float*)d_in[12];
    const float* b_i  = (const float*)d_in[13];
    const float* U_ste= (const float*)d_in[14];
    const float* b_ste= (const float*)d_in[15];
    const float* U_fre= (const float*)d_in[16];
    const float* b_fre= (const float*)d_in[17];
    const float* U_c  = (const float*)d_in[18];
    const float* b_c  = (const float*)d_in[19];
    const float* U_o  = (const float*)d_in[20];
    const float* b_o  = (const float*)d_in[21];
    const float* U_a  = (const float*)d_in[22];
    const float* b_a  = (const float*)d_in[23];
    const float* W_p  = (const float*)d_in[24];
    const float* b_p  = (const float*)d_in[25];
    const float* fc_w = (const float*)d_in[26];
    const float* fc_b = (const float*)d_in[27];
    float* out = (float*)d_out;

    cudaFuncSetAttribute(persist_kernel, cudaFuncAttributeMaxDynamicSharedMemorySize,
                         PS_TOTAL * 4);

    proj_kernel<<<dim3(17, 4, 128), 128>>>(sig, met, Wis, Wss, Wfs, Wcs, Wos,
                                           Wim, Wsm, Wfm, Wcm, Wom,
                                           b_i, b_ste, b_fre, b_c, b_o);
    persist_kernel<<<128, 256, PS_TOTAL * 4>>>(U_i, U_ste, U_c, U_o, U_fre, U_a, b_a,
                                               W_p, b_p, fc_w, fc_b, out);
}

// round 14
// speedup vs baseline: 1.1551x; 1.0729x over previous
#include <cuda_runtime.h>
#include <math.h>

#define BB 256
#define TT 128
#define HH 256
#define FF 16
#define GG 1040   // 4*H + F

// ---- static device scratch ----
__device__ float g_xproj[TT * GG * BB];   // [t][g][b]
__device__ float g_h[2][HH * BB];         // [j][b], double buffered
__device__ unsigned g_bars[16 * 32];      // per-group barrier counters, padded 128B

__device__ __forceinline__ float hsig(float x) {
    return __saturatef(x * 0.16666667f + 0.5f);
}
__device__ __forceinline__ float ftanh(float x) {
    float e = __expf(2.0f * x);
    return 1.0f - __fdividef(2.0f, e + 1.0f);
}

// ---------------- phase 0: input projection ----------------
__global__ void proj_kernel(
    const float* __restrict__ sig, const float* __restrict__ met,
    const float* __restrict__ Wis, const float* __restrict__ Wss, const float* __restrict__ Wfs,
    const float* __restrict__ Wcs, const float* __restrict__ Wos,
    const float* __restrict__ Wim, const float* __restrict__ Wsm, const float* __restrict__ Wfm,
    const float* __restrict__ Wcm, const float* __restrict__ Wom,
    const float* __restrict__ b_i, const float* __restrict__ b_ste, const float* __restrict__ b_fre,
    const float* __restrict__ b_c, const float* __restrict__ b_o)
{
    __shared__ float A_s[96 * 64];   // [k][b]
    __shared__ float B_s[96 * 64];   // [k][n]
    const int n0 = blockIdx.x * 64;
    const int b0 = blockIdx.y * 64;
    const int t  = blockIdx.z;
    const int tid = threadIdx.x;

    // reset persistent-kernel barriers (stream order: proj completes before persist)
    if (blockIdx.x == 0 && blockIdx.y == 0 && blockIdx.z == 0 && tid < 16)
        g_bars[tid * 32] = 0u;

    for (int idx = tid; idx < 64 * 96; idx += 128) {
        int b = idx / 96, k = idx - b * 96;
        float v = (k < 64) ? sig[((b0 + b) * TT + t) * 64 + k]
                           : met[((b0 + b) * TT + t) * 32 + (k - 64)];
        A_s[k * 64 + b] = v;
    }
    for (int idx = tid; idx < 96 * 64; idx += 128) {
        int k = idx >> 6, n = idx & 63;
        int g = n0 + n;
        float v = 0.f;
        if (g < 1024) {
            int gate = g >> 8, j = g & 255;
            const float* Ws = (gate == 0) ? Wis : (gate == 1) ? Wss : (gate == 2) ? Wcs : Wos;
            const float* Wm = (gate == 0) ? Wim : (gate == 1) ? Wsm : (gate == 2) ? Wcm : Wom;
            v = (k < 64) ? Ws[k * 256 + j] : Wm[(k - 64) * 256 + j];
        } else if (g < GG) {
            int f = g - 1024;
            v = (k < 64) ? Wfs[k * 16 + f] : Wfm[(k - 64) * 16 + f];
        }
        B_s[k * 64 + n] = v;
    }
    __syncthreads();

    const int tm = tid & 7, tn = tid >> 3;
    const int mb = tm * 8, nb = tn * 4;
    float acc[8][4] = {};
    for (int k = 0; k < 96; k++) {
        float4 a0 = *(const float4*)&A_s[k * 64 + mb];
        float4 a1 = *(const float4*)&A_s[k * 64 + mb + 4];
        float4 bv = *(const float4*)&B_s[k * 64 + nb];
        float am[8] = {a0.x, a0.y, a0.z, a0.w, a1.x, a1.y, a1.z, a1.w};
#pragma unroll
        for (int i = 0; i < 8; i++) {
            acc[i][0] += am[i] * bv.x; acc[i][1] += am[i] * bv.y;
            acc[i][2] += am[i] * bv.z; acc[i][3] += am[i] * bv.w;
        }
    }
#pragma unroll
    for (int q = 0; q < 4; q++) {
        int g = n0 + nb + q;
        if (g >= GG) continue;
        float bias;
        if (g < 1024) {
            int gate = g >> 8, j = g & 255;
            bias = (gate == 0) ? b_i[j] : (gate == 1) ? b_ste[j] : (gate == 2) ? b_c[j] : b_o[j];
        } else {
            bias = b_fre[g - 1024];
        }
        float4 w0, w1;
        w0.x = acc[0][q] + bias; w0.y = acc[1][q] + bias;
        w0.z = acc[2][q] + bias; w0.w = acc[3][q] + bias;
        w1.x = acc[4][q] + bias; w1.y = acc[5][q] + bias;
        w1.z = acc[6][q] + bias; w1.w = acc[7][q] + bias;
        float* dst = &g_xproj[(t * GG + g) * BB + b0 + mb];
        *(float4*)dst = w0;
        *(float4*)(dst + 4) = w1;
    }
}

// ---------------- persistent recurrence kernel ----------------
// 128 CTAs = 16 groups (16 b each) x 8 ranks (32 j each), 512 threads (16 warps).
// Proven step skeleton: stage h -> sync -> GEMM/helpers -> sync -> consumer ->
// fence -> sync -> arrive/poll -> sync. No conditional waits.
#define PS_U     0                        // [k=256][144]: 0-127 gates (gate*32+jj), 128-143 fre
#define PS_H     (PS_U + 256 * 144)       // [k=256][16]
#define PS_GT    (PS_H + 256 * 16)        // [144][20]
#define PS_X     (PS_GT + 144 * 20)       // 2 x [144][16] xproj double buffer
#define PS_RE    (PS_X + 2 * 144 * 16)    // [128][16] cos
#define PS_IM    (PS_RE + 2048)           // [128][16] sin
#define PS_UA    (PS_IM + 2048)
#define PS_BA    (PS_UA + 16)
#define PS_TOTAL (PS_BA + 32)

__global__ void __launch_bounds__(512, 1) persist_kernel(
    const float* __restrict__ U_i, const float* __restrict__ U_ste,
    const float* __restrict__ U_c, const float* __restrict__ U_o,
    const float* __restrict__ U_fre, const float* __restrict__ U_a,
    const float* __restrict__ b_a,
    const float* __restrict__ W_p, const float* __restrict__ b_p,
    const float* __restrict__ fc_w, const float* __restrict__ fc_b,
    float* __restrict__ out)
{
    extern __shared__ float sm[];
    float* U_s  = sm + PS_U;
    float* h_s  = sm + PS_H;
    float* gt_s = sm + PS_GT;
    float* x_s  = sm + PS_X;
    float* re_t = sm + PS_RE;
    float* im_t = sm + PS_IM;
    float* Ua_s = sm + PS_UA;
    float* ba_s = sm + PS_BA;

    const int tid = threadIdx.x;
    const int grp = blockIdx.x & 15;     // b-group (16 b)
    const int rnk = blockIdx.x >> 4;     // j-rank (32 j)
    const int b0 = grp * 16, j0 = rnk * 32;
    unsigned* my_bar = &g_bars[grp * 32];

    // ---- one-time staging: U gate columns for this j-slice ----
    for (int idx = tid; idx < 256 * 128; idx += 512) {
        int k = idx >> 7, c = idx & 127;
        int gate = c >> 5, jj = c & 31;
        const float* U = (gate == 0) ? U_i : (gate == 1) ? U_ste : (gate == 2) ? U_c : U_o;
        U_s[k * 144 + c] = U[k * 256 + j0 + jj];
    }
    for (int idx = tid; idx < 256 * 16; idx += 512) {
        int k = idx >> 4, f = idx & 15;
        U_s[k * 144 + 128 + f] = U_fre[k * 16 + f];
    }
    for (int idx = tid; idx < TT * 16; idx += 512) {
        int tt = idx >> 4, f = idx & 15;
        float ang = 6.2831855f * (float)(tt + 1) * ((float)f * 0.0625f);
        float sv, cv;
        sincosf(ang, &sv, &cv);
        re_t[idx] = cv; im_t[idx] = sv;
    }
    if (tid < 16) Ua_s[tid] = U_a[tid];
    if (tid >= 32 && tid < 64) ba_s[tid - 32] = b_a[j0 + tid - 32];

    // ---- prefetch xproj for t=0 into parity-0 buffer ----
    for (int idx4 = tid; idx4 < 576; idx4 += 512) {
        int g = idx4 >> 2, bq = idx4 & 3;
        int src_g = (g < 128) ? ((g >> 5) * 256 + j0 + (g & 31)) : (1024 + (g - 128));
        float4 v = *(const float4*)&g_xproj[src_g * BB + b0 + bq * 4];
        *(float4*)&x_s[g * 16 + bq * 4] = v;
    }

    // ---- S state in registers: 1 (b, jj) pair per thread ----
    float Sre[16], Sim[16];
#pragma unroll
    for (int f = 0; f < 16; f++) { Sre[f] = 0.f; Sim[f] = 0.f; }

    const int c_jj = tid >> 4;          // 0..31
    const int c_b  = tid & 15;          // 0..15

    for (int t = 0; t < TT; t++) {
        // ---- stage h(t): [k=256][16 b] (zeros at t=0) ----
        if (t == 0) {
            const float4 z = make_float4(0.f, 0.f, 0.f, 0.f);
            for (int idx = tid; idx < 1024; idx += 512)
                *(float4*)&h_s[idx * 4] = z;
        } else {
            const float* hin = &g_h[t & 1][0];
            for (int idx = tid; idx < 1024; idx += 512) {
                int k = idx >> 2, q = idx & 3;
                float4 v = __ldcg((const float4*)&hin[k * 256 + b0 + q * 4]);
                *(float4*)&h_s[k * 16 + q * 4] = v;
            }
        }
        __syncthreads();

        const float* xc = x_s + (t & 1) * (144 * 16);
        float* xn = x_s + ((t + 1) & 1) * (144 * 16);

        if (tid < 256) {
            // ---- gates GEMM: 16b x 128g on 8 warps ----
            // warp w: g in [w*16, w*16+16); lane l: bq = l&7 (b pair), gq = l>>3 (g quad)
            const int w  = tid >> 5, l = tid & 31;
            const int bq = l & 7, gq = l >> 3;
            const int gb = w * 16 + gq * 4;
            const float* hp = h_s + bq * 2;
            const float* up = U_s + gb;
            float a00 = 0.f, a01 = 0.f, a02 = 0.f, a03 = 0.f;
            float a10 = 0.f, a11 = 0.f, a12 = 0.f, a13 = 0.f;
#pragma unroll 4
            for (int k = 0; k < 256; k++) {
                float2 hv = *(const float2*)(hp + k * 16);
                float4 uv = *(const float4*)(up + k * 144);
                a00 += hv.x * uv.x; a01 += hv.x * uv.y; a02 += hv.x * uv.z; a03 += hv.x * uv.w;
                a10 += hv.y * uv.x; a11 += hv.y * uv.y; a12 += hv.y * uv.z; a13 += hv.y * uv.w;
            }
            const int bb = bq * 2;
            *(float2*)&gt_s[(gb + 0) * 20 + bb] = make_float2(a00, a10);
            *(float2*)&gt_s[(gb + 1) * 20 + bb] = make_float2(a01, a11);
            *(float2*)&gt_s[(gb + 2) * 20 + bb] = make_float2(a02, a12);
            *(float2*)&gt_s[(gb + 3) * 20 + bb] = make_float2(a03, a13);
        } else if (tid < 320) {
            // ---- fre matvec: 16b x 16f on 2 warps; thread: 2b x 2f ----
            const int s = tid - 256;         // 0..63
            const int bq = s & 7, fp = s >> 3;   // f pair
            const float* hp = h_s + bq * 2;
            const float* up = U_s + 128 + fp * 2;
            float a00 = 0.f, a01 = 0.f, a10 = 0.f, a11 = 0.f;
#pragma unroll 4
            for (int k = 0; k < 256; k++) {
                float2 hv = *(const float2*)(hp + k * 16);
                float2 uv = *(const float2*)(up + k * 144);
                a00 += hv.x * uv.x; a01 += hv.x * uv.y;
                a10 += hv.y * uv.x; a11 += hv.y * uv.y;
            }
            const int bb = bq * 2;
            *(float2*)&gt_s[(128 + fp * 2 + 0) * 20 + bb] = make_float2(a00, a10);
            *(float2*)&gt_s[(128 + fp * 2 + 1) * 20 + bb] = make_float2(a01, a11);
        } else {
            // ---- x(t+1) prefetch on 6 warps: 576 float4 / 192 threads = 3 each ----
            if (t + 1 < TT) {
                const int s = tid - 320;     // 0..191
                const int xt = (t + 1) * GG * BB;
                float4 r[3];
#pragma unroll
                for (int i = 0; i < 3; i++) {
                    int idx4 = s + i * 192;
                    int g = idx4 >> 2, bq2 = idx4 & 3;
                    int src_g = (g < 128) ? ((g >> 5) * 256 + j0 + (g & 31)) : (1024 + (g - 128));
                    r[i] = *(const float4*)&g_xproj[xt + src_g * BB + b0 + bq2 * 4];
                }
#pragma unroll
                for (int i = 0; i < 3; i++) {
                    int idx4 = s + i * 192;
                    int g = idx4 >> 2, bq2 = idx4 & 3;
                    *(float4*)&xn[g * 16 + bq2 * 4] = r[i];
                }
            }
        }
        __syncthreads();

        // ---- consumer: 1 (b, jj) pair per thread, S in registers ----
        {
            float* hout = &g_h[(t & 1) ^ 1][0];
            const float* ret = re_t + t * 16;
            const float* imt = im_t + t * 16;
            const int b = c_b;
            float gi  = hsig(gt_s[(      c_jj) * 20 + b] + xc[(      c_jj) * 16 + b]);
            float ste = hsig(gt_s[( 32 + c_jj) * 20 + b] + xc[( 32 + c_jj) * 16 + b]);
            float cg  = gi * ftanh(gt_s[( 64 + c_jj) * 20 + b] + xc[( 64 + c_jj) * 16 + b]);
            float o   = hsig(gt_s[( 96 + c_jj) * 20 + b] + xc[( 96 + c_jj) * 16 + b]);
            float Aa = 0.f;
#pragma unroll
            for (int f = 0; f < 16; f++) {
                float fre = hsig(gt_s[(128 + f) * 20 + b] + xc[(128 + f) * 16 + b]);
                float fv = ste * fre;
                float nr = fv * Sre[f] + cg * ret[f];
                float ni = fv * Sim[f] + cg * imt[f];
                Sre[f] = nr; Sim[f] = ni;
                Aa += (nr * nr + ni * ni) * Ua_s[f];
            }
            float a = ftanh(Aa + ba_s[c_jj]);
            __stcg(&hout[(j0 + c_jj) * 256 + b0 + c_b], o * a);
        }

        // ---- per-group barrier (8 CTAs sharing this b-group) ----
        __threadfence();
        __syncthreads();
        if (tid == 0) {
            atomicAdd(my_bar, 1u);
            const unsigned target = 8u * (unsigned)(t + 1);
            while (*(volatile unsigned*)my_bar < target) { }
        }
        __syncthreads();
    }

    // ---- output head: rank-0 CTA of each group computes its 16 outputs ----
    if (rnk == 0) {
        const float* h = &g_h[0][0];   // h(128): t=127 wrote buffer 0
        const int b = b0 + (tid & 15);
        const int jr = (tid >> 4) * 8;
        float s = 0.f;
#pragma unroll 4
        for (int j = jr; j < jr + 8; j++) s += __ldcg(&h[j * 256 + b]) * W_p[j];
        gt_s[(tid >> 4) * 20 + (tid & 15)] = s;
        __syncthreads();
        if (tid < 16) {
            float acc = 0.f;
#pragma unroll
            for (int q = 0; q < 32; q++) acc += gt_s[q * 20 + tid];
            float p = acc + b_p[0];
            out[b0 + tid] = p * fc_w[0] + fc_b[0];
        }
    }
}

// ---------------- launch ----------------
extern "C" void kernel_launch(void* const* d_in, const int* in_sizes, int n_in,
                              void* d_out, int out_size)
{
    const float* sig  = (const float*)d_in[0];
    const float* met  = (const float*)d_in[1];
    const float* Wis  = (const float*)d_in[2];
    const float* Wss  = (const float*)d_in[3];
    const float* Wfs  = (const float*)d_in[4];
    const float* Wcs  = (const float*)d_in[5];
    const float* Wos  = (const float*)d_in[6];
    const float* Wim  = (const float*)d_in[7];
    const float* Wsm  = (const float*)d_in[8];
    const float* Wfm  = (const float*)d_in[9];
    const float* Wcm  = (const float*)d_in[10];
    const float* Wom  = (const float*)d_in[11];
    const float* U_i  = (const float*)d_in[12];
    const float* b_i  = (const float*)d_in[13];
    const float* U_ste= (const float*)d_in[14];
    const float* b_ste= (const float*)d_in[15];
    const float* U_fre= (const float*)d_in[16];
    const float* b_fre= (const float*)d_in[17];
    const float* U_c  = (const float*)d_in[18];
    const float* b_c  = (const float*)d_in[19];
    const float* U_o  = (const float*)d_in[20];
    const float* b_o  = (const float*)d_in[21];
    const float* U_a  = (const float*)d_in[22];
    const float* b_a  = (const float*)d_in[23];
    const float* W_p  = (const float*)d_in[24];
    const float* b_p  = (const float*)d_in[25];
    const float* fc_w = (const float*)d_in[26];
    const float* fc_b = (const float*)d_in[27];
    float* out = (float*)d_out;

    cudaFuncSetAttribute(persist_kernel, cudaFuncAttributeMaxDynamicSharedMemorySize,
                         PS_TOTAL * 4);

    proj_kernel<<<dim3(17, 4, 128), 128>>>(sig, met, Wis, Wss, Wfs, Wcs, Wos,
                                           Wim, Wsm, Wfm, Wcm, Wom,
                                           b_i, b_ste, b_fre, b_c, b_o);
    persist_kernel<<<128, 512, PS_TOTAL * 4>>>(U_i, U_ste, U_c, U_o, U_fre, U_a, b_a,
                                               W_p, b_p, fc_w, fc_b, out);
}